// round 1
// baseline (speedup 1.0000x reference)
#include <cuda_runtime.h>

#define H_   768
#define L_   10
#define W_   10
#define B_   512
#define T_   10
#define G4H  (4 * H_)

// ---------------- scratch (static device globals; no allocation) ----------------
__device__ float g_bufA[T_ * B_ * H_];     // 15.7 MB
__device__ float g_bufB[T_ * B_ * H_];     // 15.7 MB
__device__ float g_gx[T_ * B_ * G4H];      // 62.9 MB
__device__ float g_c[B_ * H_];             // 1.5 MB

// ---------------- transpose (B,W,H) -> (W,B,H) ----------------
__global__ __launch_bounds__(256) void transpose_in(const float* __restrict__ xp,
                                                    float* __restrict__ out) {
    int idx = blockIdx.x * 256 + threadIdx.x;      // idx = (w*B + b)*H + h
    if (idx >= T_ * B_ * H_) return;
    int h = idx % H_;
    int r = idx / H_;
    int b = r % B_;
    int w = r / B_;
    out[idx] = xp[((size_t)b * W_ + w) * H_ + h];
}

// ---------------- (W,B,H) -> (B, W*H) concat ----------------
__global__ __launch_bounds__(256) void make_xcat(const float* __restrict__ X,
                                                 float* __restrict__ xcat) {
    int idx = blockIdx.x * 256 + threadIdx.x;      // idx = (b*W + w)*H + h
    if (idx >= T_ * B_ * H_) return;
    int h = idx % H_;
    int r = idx / H_;
    int w = r % W_;
    int b = r / W_;
    xcat[idx] = X[((size_t)w * B_ + b) * H_ + h];
}

// ---------------- LSTM cell elementwise ----------------
__global__ __launch_bounds__(256) void lstm_cell(const float* __restrict__ g,
                                                 float* __restrict__ c,
                                                 float* __restrict__ hout, int t) {
    int idx = blockIdx.x * 256 + threadIdx.x;      // b*H + j
    if (idx >= B_ * H_) return;
    int b = idx / H_;
    int j = idx % H_;
    const float* gr = g + (size_t)b * G4H;
    float gi = gr[j];
    float gf = gr[H_ + j];
    float gg = gr[2 * H_ + j];
    float go = gr[3 * H_ + j];
    float i = 1.f / (1.f + __expf(-gi));
    float f = 1.f / (1.f + __expf(-gf));
    float gt = tanhf(gg);
    float o = 1.f / (1.f + __expf(-go));
    float cprev = (t == 0) ? 0.f : c[idx];
    float cn = f * cprev + i * gt;
    c[idx] = cn;
    hout[idx] = o * tanhf(cn);
}

// ---------------- SGEMM: C[M,N] (+)= A[M,K] * Wt[N,K]^T (+ bias1 + bias2) -------
// BM=BN=128, BK=8, 256 threads, 8x8 per thread. Requires M%128==0, N%128==0, K%8==0.
__global__ __launch_bounds__(256) void sgemm_nt(const float* __restrict__ A,
                                                const float* __restrict__ Wt,
                                                const float* __restrict__ bias1,
                                                const float* __restrict__ bias2,
                                                float* __restrict__ C,
                                                int N, int K, int accumulate) {
    constexpr int BM = 128, BN = 128, BK = 8, TM = 8, TN = 8;
    __shared__ float As[BK][BM];
    __shared__ float Bs[BK][BN];

    const int bm = blockIdx.y * BM;
    const int bn = blockIdx.x * BN;
    const int tid = threadIdx.x;

    const int arow = tid >> 1;          // 0..127
    const int acol = (tid & 1) * 4;     // 0 or 4
    const int tr = (tid >> 4) * TM;     // micro-tile row
    const int tc = (tid & 15) * TN;     // micro-tile col

    float acc[TM][TN];
#pragma unroll
    for (int i = 0; i < TM; i++)
#pragma unroll
        for (int j = 0; j < TN; j++) acc[i][j] = 0.f;

    const float* Aptr = A + (size_t)(bm + arow) * K + acol;
    const float* Bptr = Wt + (size_t)(bn + arow) * K + acol;

    for (int k0 = 0; k0 < K; k0 += BK) {
        float4 av = *reinterpret_cast<const float4*>(Aptr + k0);
        As[acol + 0][arow] = av.x;
        As[acol + 1][arow] = av.y;
        As[acol + 2][arow] = av.z;
        As[acol + 3][arow] = av.w;
        float4 bv = *reinterpret_cast<const float4*>(Bptr + k0);
        Bs[acol + 0][arow] = bv.x;
        Bs[acol + 1][arow] = bv.y;
        Bs[acol + 2][arow] = bv.z;
        Bs[acol + 3][arow] = bv.w;
        __syncthreads();
#pragma unroll
        for (int k = 0; k < BK; k++) {
            float ar[TM], br[TN];
#pragma unroll
            for (int i = 0; i < TM; i++) ar[i] = As[k][tr + i];
#pragma unroll
            for (int j = 0; j < TN; j++) br[j] = Bs[k][tc + j];
#pragma unroll
            for (int i = 0; i < TM; i++)
#pragma unroll
                for (int j = 0; j < TN; j++) acc[i][j] = fmaf(ar[i], br[j], acc[i][j]);
        }
        __syncthreads();
    }

    // bias for this thread's 8 columns
    float bv[TN];
#pragma unroll
    for (int j = 0; j < TN; j++) {
        float v = 0.f;
        if (bias1) v += bias1[bn + tc + j];
        if (bias2) v += bias2[bn + tc + j];
        bv[j] = v;
    }

#pragma unroll
    for (int i = 0; i < TM; i++) {
        size_t crow = (size_t)(bm + tr + i) * N + bn + tc;
#pragma unroll
        for (int j4 = 0; j4 < TN; j4 += 4) {
            float4* cp = reinterpret_cast<float4*>(C + crow + j4);
            float4 v;
            v.x = acc[i][j4 + 0] + bv[j4 + 0];
            v.y = acc[i][j4 + 1] + bv[j4 + 1];
            v.z = acc[i][j4 + 2] + bv[j4 + 2];
            v.w = acc[i][j4 + 3] + bv[j4 + 3];
            if (accumulate) {
                float4 o = *cp;
                v.x += o.x; v.y += o.y; v.z += o.z; v.w += o.w;
            }
            *cp = v;
        }
    }
}

// ---------------- launcher ----------------
extern "C" void kernel_launch(void* const* d_in, const int* in_sizes, int n_in,
                              void* d_out, int out_size) {
    const float* xp    = (const float*)d_in[0];  // (B, W, 256, 3) = (B, W, H)
    const float* fc0_w = (const float*)d_in[1];  // (H, H)
    const float* fc0_b = (const float*)d_in[2];  // (H)
    const float* w_ih  = (const float*)d_in[3];  // (L, 4H, H)
    const float* w_hh  = (const float*)d_in[4];  // (L, 4H, H)
    const float* b_ih  = (const float*)d_in[5];  // (L, 4H)
    const float* b_hh  = (const float*)d_in[6];  // (L, 4H)
    const float* fc1_w = (const float*)d_in[7];  // (H, H*W)
    const float* fc1_b = (const float*)d_in[8];  // (H)
    float* out = (float*)d_out;                  // (B*H) fp32 = (B*256,3)

    float *bufA, *bufB, *gx, *cbuf;
    cudaGetSymbolAddress((void**)&bufA, g_bufA);
    cudaGetSymbolAddress((void**)&bufB, g_bufB);
    cudaGetSymbolAddress((void**)&gx,   g_gx);
    cudaGetSymbolAddress((void**)&cbuf, g_c);

    const int nElems = T_ * B_ * H_;

    // 1) transpose input (B,W,H)->(W,B,H) into bufB
    transpose_in<<<(nElems + 255) / 256, 256>>>(xp, bufB);

    // 2) fc0: bufA = bufB @ fc0_w^T + fc0_b   (M=5120, N=768, K=768)
    {
        dim3 g(H_ / 128, (T_ * B_) / 128);
        sgemm_nt<<<g, 256>>>(bufB, fc0_w, fc0_b, nullptr, bufA, H_, H_, 0);
    }

    float* Xin = bufA;
    float* Xout = bufB;

    for (int l = 0; l < L_; l++) {
        const float* wih = w_ih + (size_t)l * G4H * H_;
        const float* whh = w_hh + (size_t)l * G4H * H_;
        const float* bih = b_ih + (size_t)l * G4H;
        const float* bhh = b_hh + (size_t)l * G4H;

        // gx = Xin @ wih^T + bih + bhh   (M=5120, N=3072, K=768)
        {
            dim3 g(G4H / 128, (T_ * B_) / 128);
            sgemm_nt<<<g, 256>>>(Xin, wih, bih, bhh, gx, G4H, H_, 0);
        }

        for (int t = 0; t < T_; t++) {
            float* gt = gx + (size_t)t * B_ * G4H;
            if (t > 0) {
                // gt += h_{t-1} @ whh^T   (M=512, N=3072, K=768)
                dim3 g(G4H / 128, B_ / 128);
                sgemm_nt<<<g, 256>>>(Xout + (size_t)(t - 1) * B_ * H_, whh,
                                     nullptr, nullptr, gt, G4H, H_, 1);
            }
            lstm_cell<<<(B_ * H_ + 255) / 256, 256>>>(
                gt, cbuf, Xout + (size_t)t * B_ * H_, t);
        }
        // swap
        float* tmp = Xin; Xin = Xout; Xout = tmp;
    }

    // Final sequence output now in Xin (after even number of swaps). Concat into Xout.
    make_xcat<<<(nElems + 255) / 256, 256>>>(Xin, Xout);

    // fc1: out = xcat @ fc1_w^T + fc1_b   (M=512, N=768, K=7680)
    {
        dim3 g(H_ / 128, B_ / 128);
        sgemm_nt<<<g, 256>>>(Xout, fc1_w, fc1_b, nullptr, out, H_, W_ * H_, 0);
    }
}

// round 15
// speedup vs baseline: 2.1622x; 2.1622x over previous
#include <cuda_runtime.h>
#include <cuda_fp16.h>
#include <mma.h>
#include <cstdint>

using namespace nvcuda;

#define H_   768
#define L_   10
#define W_   10
#define B_   512
#define T_   10
#define G4H  (4 * H_)

// ---------------- scratch (static device globals; no allocation) ----------------
__device__ __half g_wih_h[L_ * G4H * H_];   // 47 MB
__device__ __half g_whh_h[L_ * G4H * H_];   // 47 MB
__device__ __half g_fc0_h[H_ * H_];
__device__ __half g_fc1_h[H_ * W_ * H_];
__device__ __half g_xa[T_ * B_ * H_];       // 7.9 MB
__device__ __half g_xb[T_ * B_ * H_];
__device__ __half g_xcat[T_ * B_ * H_];
__device__ float  g_gx[T_ * B_ * G4H];      // 63 MB
__device__ float  g_gh[B_ * G4H];           // 6.3 MB
__device__ float  g_c[B_ * H_];

// ---------------- cp.async helpers ----------------
__device__ __forceinline__ uint32_t smem_u32(const void* p) {
    uint32_t a;
    asm("{ .reg .u64 t; cvta.to.shared.u64 t, %1; cvt.u32.u64 %0, t; }" : "=r"(a) : "l"(p));
    return a;
}
__device__ __forceinline__ void cp16(uint32_t dst, const void* src) {
    asm volatile("cp.async.cg.shared.global [%0], [%1], 16;\n" :: "r"(dst), "l"(src) : "memory");
}

// ---------------- wmma fp16 GEMM: C[M,N] = A[M,K] @ Wt[N,K]^T (+bias) -----------
// A, Wt fp16 K-major (row-major MxK / NxK). M%128==0, N%128==0, K%32==0.
// Cf32 / Cf16 optional simultaneous outputs.
#define BM 128
#define BN 128
#define BK 32
#define LDS_ 40                                // padded half stride (80B, 16B-aligned)
#define A_TILE_B (BM * LDS_ * 2)               // 10240 B
#define STAGE_B  (2 * A_TILE_B)                // A + B tiles
#define STAGING_OFF (2 * STAGE_B)              // after 2 stages = 40960
#define GEMM_SMEM (STAGING_OFF + 8 * 256 * 4)  // + 8KB staging = 49152

__global__ __launch_bounds__(256)
void gemm_wmma(const __half* __restrict__ A, const __half* __restrict__ Wt,
               const float* __restrict__ bias1, const float* __restrict__ bias2,
               float* __restrict__ Cf32, __half* __restrict__ Cf16, int N, int K) {
    extern __shared__ char smem[];
    const uint32_t sb = smem_u32(smem);
    const int tid = threadIdx.x;
    const int wid = tid >> 5, lid = tid & 31;
    const int wm = wid >> 1;            // 0..3 : 32-row band
    const int wn = wid & 1;             // 0..1 : 64-col band
    const int bm = blockIdx.y * BM, bn = blockIdx.x * BN;
    const int KT = K / BK;

    wmma::fragment<wmma::accumulator, 16, 16, 16, float> acc[2][4];
#pragma unroll
    for (int i = 0; i < 2; i++)
#pragma unroll
        for (int j = 0; j < 4; j++) wmma::fill_fragment(acc[i][j], 0.0f);

    auto issue_loads = [&](int kt, int s) {
        uint32_t abase = sb + s * STAGE_B;
        uint32_t bbase = abase + A_TILE_B;
        const __half* Ab = A + (size_t)bm * K + kt * BK;
        const __half* Bb = Wt + (size_t)bn * K + kt * BK;
#pragma unroll
        for (int i = 0; i < 2; i++) {
            int c = tid + i * 256;          // 0..511 chunks of 16B (4 per row)
            int row = c >> 2;
            int e = c & 3;                  // 16B chunk within the 64B row
            uint32_t so = row * (LDS_ * 2) + e * 16;
            cp16(abase + so, Ab + (size_t)row * K + e * 8);
            cp16(bbase + so, Bb + (size_t)row * K + e * 8);
        }
        asm volatile("cp.async.commit_group;\n" ::: "memory");
    };

    issue_loads(0, 0);

    for (int kt = 0; kt < KT; kt++) {
        const int s = kt & 1;
        if (kt + 1 < KT) issue_loads(kt + 1, s ^ 1);

        if (kt + 1 < KT) asm volatile("cp.async.wait_group 1;\n" ::: "memory");
        else             asm volatile("cp.async.wait_group 0;\n" ::: "memory");
        __syncthreads();

        const __half* As = reinterpret_cast<const __half*>(smem + s * STAGE_B);
        const __half* Bs = reinterpret_cast<const __half*>(smem + s * STAGE_B + A_TILE_B);

#pragma unroll
        for (int k2 = 0; k2 < 2; k2++) {
            wmma::fragment<wmma::matrix_a, 16, 16, 16, __half, wmma::row_major> fa[2];
            wmma::fragment<wmma::matrix_b, 16, 16, 16, __half, wmma::col_major> fb[4];
#pragma unroll
            for (int i = 0; i < 2; i++)
                wmma::load_matrix_sync(fa[i], As + (wm * 32 + i * 16) * LDS_ + k2 * 16, LDS_);
#pragma unroll
            for (int j = 0; j < 4; j++)
                wmma::load_matrix_sync(fb[j], Bs + (wn * 64 + j * 16) * LDS_ + k2 * 16, LDS_);
#pragma unroll
            for (int i = 0; i < 2; i++)
#pragma unroll
                for (int j = 0; j < 4; j++)
                    wmma::mma_sync(acc[i][j], fa[i], fb[j], acc[i][j]);
        }
        __syncthreads();   // stage s gets refilled next iteration
    }

    // ---- epilogue: stage each 16x16 tile through smem, add bias, store ----
    float* st = reinterpret_cast<float*>(smem + STAGING_OFF) + wid * 256;
#pragma unroll
    for (int i = 0; i < 2; i++) {
#pragma unroll
        for (int j = 0; j < 4; j++) {
            wmma::store_matrix_sync(st, acc[i][j], 16, wmma::mem_row_major);
            __syncwarp();
            const int r0 = bm + wm * 32 + i * 16;
            const int c0 = bn + wn * 64 + j * 16;
#pragma unroll
            for (int q = 0; q < 8; q++) {
                int idx = lid * 8 + q;
                int r = idx >> 4, c = idx & 15;
                float v = st[idx];
                int col = c0 + c;
                if (bias1) v += bias1[col];
                if (bias2) v += bias2[col];
                size_t off = (size_t)(r0 + r) * N + col;
                if (Cf32) Cf32[off] = v;
                if (Cf16) Cf16[off] = __float2half_rn(v);
            }
            __syncwarp();
        }
    }
}

// ---------------- fp32 -> fp16 convert ----------------
__global__ __launch_bounds__(256) void f32_to_f16_vec(const float* __restrict__ in,
                                                      __half* __restrict__ out, int n4) {
    int i = blockIdx.x * 256 + threadIdx.x;
    if (i >= n4) return;
    float4 v = reinterpret_cast<const float4*>(in)[i];
    reinterpret_cast<__half2*>(out)[2 * i + 0] = __floats2half2_rn(v.x, v.y);
    reinterpret_cast<__half2*>(out)[2 * i + 1] = __floats2half2_rn(v.z, v.w);
}

// ---------------- transpose (B,W,H) fp32 -> (W,B,H) fp16 ----------------
__global__ __launch_bounds__(256) void transpose_in_f16(const float* __restrict__ xp,
                                                        __half* __restrict__ out) {
    int idx = blockIdx.x * 256 + threadIdx.x;      // (w*B + b)*H + h
    if (idx >= T_ * B_ * H_) return;
    int h = idx % H_;
    int r = idx / H_;
    int b = r % B_;
    int w = r / B_;
    out[idx] = __float2half_rn(xp[((size_t)b * W_ + w) * H_ + h]);
}

// ---------------- (W,B,H) fp16 -> (B, W*H) fp16 ----------------
__global__ __launch_bounds__(256) void make_xcat_f16(const __half* __restrict__ X,
                                                     __half* __restrict__ xcat) {
    int idx = blockIdx.x * 256 + threadIdx.x;      // (b*W + w)*H + h
    if (idx >= T_ * B_ * H_) return;
    int h = idx % H_;
    int r = idx / H_;
    int w = r % W_;
    int b = r / W_;
    xcat[idx] = X[((size_t)w * B_ + b) * H_ + h];
}

// ---------------- LSTM cell: gates = gx + gh; h out as fp16 ----------------
__global__ __launch_bounds__(256) void lstm_cell2(const float* __restrict__ gx,
                                                  const float* __restrict__ gh,
                                                  float* __restrict__ c,
                                                  __half* __restrict__ hout, int t) {
    int i = blockIdx.x * 256 + threadIdx.x;        // over B*H/4
    if (i >= B_ * H_ / 4) return;
    int j4 = i % (H_ / 4);
    int b = i / (H_ / 4);
    const float4* gr = reinterpret_cast<const float4*>(gx + (size_t)b * G4H);
    float4 gi = gr[j4];
    float4 gf = gr[(H_ / 4) + j4];
    float4 gg = gr[(2 * H_ / 4) + j4];
    float4 go = gr[(3 * H_ / 4) + j4];
    if (gh) {
        const float4* gr2 = reinterpret_cast<const float4*>(gh + (size_t)b * G4H);
        float4 a;
        a = gr2[j4];                gi.x += a.x; gi.y += a.y; gi.z += a.z; gi.w += a.w;
        a = gr2[(H_ / 4) + j4];     gf.x += a.x; gf.y += a.y; gf.z += a.z; gf.w += a.w;
        a = gr2[(2 * H_ / 4) + j4]; gg.x += a.x; gg.y += a.y; gg.z += a.z; gg.w += a.w;
        a = gr2[(3 * H_ / 4) + j4]; go.x += a.x; go.y += a.y; go.z += a.z; go.w += a.w;
    }
    float iv[4] = {gi.x, gi.y, gi.z, gi.w};
    float fv[4] = {gf.x, gf.y, gf.z, gf.w};
    float gv[4] = {gg.x, gg.y, gg.z, gg.w};
    float ov[4] = {go.x, go.y, go.z, go.w};
    float4 cprev = make_float4(0.f, 0.f, 0.f, 0.f);
    float4* cp = reinterpret_cast<float4*>(c) + i;
    if (t > 0) cprev = *cp;
    float cv[4] = {cprev.x, cprev.y, cprev.z, cprev.w};
    float hv[4];
#pragma unroll
    for (int k = 0; k < 4; k++) {
        float ig = 1.f / (1.f + __expf(-iv[k]));
        float fg = 1.f / (1.f + __expf(-fv[k]));
        float gt = tanhf(gv[k]);
        float og = 1.f / (1.f + __expf(-ov[k]));
        float cn = fg * cv[k] + ig * gt;
        cv[k] = cn;
        hv[k] = og * tanhf(cn);
    }
    *cp = make_float4(cv[0], cv[1], cv[2], cv[3]);
    __half2* hp = reinterpret_cast<__half2*>(hout) + 2 * i;
    hp[0] = __floats2half2_rn(hv[0], hv[1]);
    hp[1] = __floats2half2_rn(hv[2], hv[3]);
}

// ---------------- launcher ----------------
extern "C" void kernel_launch(void* const* d_in, const int* in_sizes, int n_in,
                              void* d_out, int out_size) {
    const float* xp    = (const float*)d_in[0];
    const float* fc0_w = (const float*)d_in[1];
    const float* fc0_b = (const float*)d_in[2];
    const float* w_ih  = (const float*)d_in[3];
    const float* w_hh  = (const float*)d_in[4];
    const float* b_ih  = (const float*)d_in[5];
    const float* b_hh  = (const float*)d_in[6];
    const float* fc1_w = (const float*)d_in[7];
    const float* fc1_b = (const float*)d_in[8];
    float* out = (float*)d_out;

    __half *wih_h, *whh_h, *fc0_h, *fc1_h, *xa, *xb, *xcat;
    float *gx, *gh, *cbuf;
    cudaGetSymbolAddress((void**)&wih_h, g_wih_h);
    cudaGetSymbolAddress((void**)&whh_h, g_whh_h);
    cudaGetSymbolAddress((void**)&fc0_h, g_fc0_h);
    cudaGetSymbolAddress((void**)&fc1_h, g_fc1_h);
    cudaGetSymbolAddress((void**)&xa, g_xa);
    cudaGetSymbolAddress((void**)&xb, g_xb);
    cudaGetSymbolAddress((void**)&xcat, g_xcat);
    cudaGetSymbolAddress((void**)&gx, g_gx);
    cudaGetSymbolAddress((void**)&gh, g_gh);
    cudaGetSymbolAddress((void**)&cbuf, g_c);

    cudaFuncSetAttribute(gemm_wmma, cudaFuncAttributeMaxDynamicSharedMemorySize, GEMM_SMEM);

    // weight conversions
    {
        int n4 = L_ * G4H * H_ / 4;
        f32_to_f16_vec<<<(n4 + 255) / 256, 256>>>(w_ih, wih_h, n4);
        f32_to_f16_vec<<<(n4 + 255) / 256, 256>>>(w_hh, whh_h, n4);
        int n4b = H_ * H_ / 4;
        f32_to_f16_vec<<<(n4b + 255) / 256, 256>>>(fc0_w, fc0_h, n4b);
        int n4c = H_ * W_ * H_ / 4;
        f32_to_f16_vec<<<(n4c + 255) / 256, 256>>>(fc1_w, fc1_h, n4c);
    }

    const int nElems = T_ * B_ * H_;
    transpose_in_f16<<<(nElems + 255) / 256, 256>>>(xp, xa);

    // fc0: xb_f16 = xa @ fc0_w^T + fc0_b   (M=5120, N=768, K=768)
    {
        dim3 g(H_ / BN, (T_ * B_) / BM);
        gemm_wmma<<<g, 256, GEMM_SMEM>>>(xa, fc0_h, fc0_b, nullptr, nullptr, xb, H_, H_);
    }

    __half* Xin = xb;
    __half* Xout = xa;

    for (int l = 0; l < L_; l++) {
        const __half* wih = wih_h + (size_t)l * G4H * H_;
        const __half* whh = whh_h + (size_t)l * G4H * H_;
        const float* bih = b_ih + (size_t)l * G4H;
        const float* bhh = b_hh + (size_t)l * G4H;

        // gx = Xin @ wih^T + bih + bhh   (M=5120, N=3072, K=768)
        {
            dim3 g(G4H / BN, (T_ * B_) / BM);
            gemm_wmma<<<g, 256, GEMM_SMEM>>>(Xin, wih, bih, bhh, gx, nullptr, G4H, H_);
        }

        for (int t = 0; t < T_; t++) {
            float* gt = gx + (size_t)t * B_ * G4H;
            if (t > 0) {
                // gh = h_{t-1} @ whh^T   (M=512, N=3072, K=768)
                dim3 g(G4H / BN, B_ / BM);
                gemm_wmma<<<g, 256, GEMM_SMEM>>>(Xout + (size_t)(t - 1) * B_ * H_, whh,
                                                 nullptr, nullptr, gh, nullptr, G4H, H_);
            }
            lstm_cell2<<<(B_ * H_ / 4 + 255) / 256, 256>>>(
                gt, (t > 0) ? gh : nullptr, cbuf, Xout + (size_t)t * B_ * H_, t);
        }
        __half* tmp = Xin; Xin = Xout; Xout = tmp;
    }

    // concat (W,B,H) -> (B, W*H)
    make_xcat_f16<<<(nElems + 255) / 256, 256>>>(Xin, xcat);

    // fc1: out = xcat @ fc1_w^T + fc1_b   (M=512, N=768, K=7680)
    {
        dim3 g(H_ / BN, B_ / BM);
        gemm_wmma<<<g, 256, GEMM_SMEM>>>(xcat, fc1_h, fc1_b, nullptr, out, nullptr, H_, W_ * H_);
    }
}